// round 11
// baseline (speedup 1.0000x reference)
#include <cuda_runtime.h>
#include <math_constants.h>

// ---------------- Problem constants ----------------
#define ROWS      19456     // B*C*N = 16*19*64
#define INPUT_DIM 200
#define NF        101       // rfft bins
#define FFTW      208       // 2*NF padded to 208 (re/im interleaved)
#define VD        64        // VQ dim
#define NCB       8192      // codebook entries

#define SZ_X      (ROWS * INPUT_DIM)   // 38,912,000
#define SZ_PROJ   (NF * VD)            // 6,464
#define SZ_CB     (NCB * VD)           // 524,288

// ---------------- Device scratch (no allocations allowed) ----------------
__device__ float g_W[INPUT_DIM * FFTW];          // DFT matrix (cos / -sin, ortho scaled)
__device__ float g_fft[ROWS * FFTW];             // rfft output, re/im interleaved
__device__ float g_amp[ROWS * NF];
__device__ float g_phase[ROWS * NF];
__device__ float g_featT[2][VD * ROWS];          // [amp/phase][k][row]  (k-major!)
__device__ float g_cbnT[2][VD * NCB];            // normalized codebooks, k-major

// ---------------- K0: build DFT matrix (double-precision twiddles) ----------------
__global__ void build_w_kernel() {
    int i = blockIdx.x * blockDim.x + threadIdx.x;
    if (i >= INPUT_DIM * FFTW) return;
    int n = i / FFTW;
    int c = i % FFTW;
    int f = c >> 1;
    float val = 0.f;
    if (f < NF) {
        // angle = 2*pi*f*n/200 = pi * (f*n/100)
        double xa = (double)(n * f) / 100.0;
        double s, cs;
        sincospi(xa, &s, &cs);
        const double scale = 0.070710678118654752440; // 1/sqrt(200), ortho norm
        val = (c & 1) ? (float)(-s * scale) : (float)(cs * scale);
    }
    g_W[i] = val;
}

// ---------------- K1: normalize + transpose codebooks (one warp per entry) ----------------
__global__ void norm_cb_kernel(const float* __restrict__ cb_amp,
                               const float* __restrict__ cb_phase) {
    int which = blockIdx.y;
    const float* src = which ? cb_phase : cb_amp;
    int warp = threadIdx.x >> 5;
    int lane = threadIdx.x & 31;
    int m = blockIdx.x * 8 + warp;            // 1024 blocks * 8 warps = 8192
    float v0 = src[m * VD + lane];
    float v1 = src[m * VD + 32 + lane];
    float s = v0 * v0 + v1 * v1;
    #pragma unroll
    for (int o = 16; o; o >>= 1) s += __shfl_xor_sync(0xffffffffu, s, o);
    float nrm = sqrtf(s);
    float* dst = g_cbnT[which];
    dst[lane * NCB + m]        = v0 / nrm;
    dst[(lane + 32) * NCB + m] = v1 / nrm;
}

// ---------------- K2: DFT as tiled GEMM: g_fft = x[ROWS x 200] @ W[200 x 208] ----------------
// BM=64, BN=64 (4 col tiles, guard c<208), BK=40, 256 threads, 4x4 micro-tile
__global__ void dft_gemm_kernel(const float* __restrict__ x) {
    __shared__ float As[64 * 40];   // [m][k]
    __shared__ float Bs[40 * 64];   // [k][n]
    int tx = threadIdx.x & 15;
    int ty = threadIdx.x >> 4;
    int rowBase = blockIdx.x * 64;          // 304 * 64 = 19456 exact
    int colBase = blockIdx.y * 64;          // 0..255, guard 208
    float acc[4][4] = {};
    for (int kt = 0; kt < 5; ++kt) {
        int k0 = kt * 40;
        __syncthreads();
        for (int idx = threadIdx.x; idx < 64 * 40; idx += 256) {
            int mm = idx / 40, kk = idx - mm * 40;
            As[idx] = x[(rowBase + mm) * INPUT_DIM + k0 + kk];
        }
        for (int idx = threadIdx.x; idx < 40 * 64; idx += 256) {
            int kk = idx >> 6, nn = idx & 63;
            int c = colBase + nn;
            Bs[idx] = (c < FFTW) ? g_W[(k0 + kk) * FFTW + c] : 0.f;
        }
        __syncthreads();
        #pragma unroll 8
        for (int k = 0; k < 40; ++k) {
            float4 b = *reinterpret_cast<const float4*>(&Bs[k * 64 + tx * 4]);
            float bv[4] = {b.x, b.y, b.z, b.w};
            #pragma unroll
            for (int i = 0; i < 4; ++i) {
                float a = As[(ty * 4 + i) * 40 + k];
                #pragma unroll
                for (int j = 0; j < 4; ++j) acc[i][j] += a * bv[j];
            }
        }
    }
    #pragma unroll
    for (int i = 0; i < 4; ++i) {
        int r = rowBase + ty * 4 + i;
        #pragma unroll
        for (int j = 0; j < 4; ++j) {
            int c = colBase + tx * 4 + j;
            if (c < FFTW) g_fft[r * FFTW + c] = acc[i][j];
        }
    }
}

// ---------------- K3: amp / phase elementwise ----------------
__global__ void ampphase_kernel() {
    int i = blockIdx.x * blockDim.x + threadIdx.x;
    if (i >= ROWS * NF) return;
    int r = i / NF;
    int f = i - r * NF;
    float re = g_fft[r * FFTW + 2 * f];
    float im = g_fft[r * FFTW + 2 * f + 1];
    g_amp[i]   = sqrtf(re * re + im * im);
    g_phase[i] = atan2f(im, re);
}

// ---------------- K4: projection GEMM -> transposed features ----------------
// feat[r][d] = sum_k amp[r][k] * proj[k][d]; write featT[d][r].
// (L2 normalization of features is a positive per-row scale -> argmax-invariant -> skipped)
__global__ void proj_kernel(const float* __restrict__ proj_amp,
                            const float* __restrict__ proj_phase) {
    __shared__ float pjs[NF * VD];      // 101x64
    __shared__ float rows_s[4 * NF];    // 4 feature rows
    int y = blockIdx.y;
    const float* proj = y ? proj_phase : proj_amp;
    const float* src  = y ? g_phase : g_amp;
    int rowBase = blockIdx.x * 4;       // 4864 * 4 = 19456 exact
    for (int idx = threadIdx.x; idx < NF * VD; idx += 256) pjs[idx] = proj[idx];
    for (int idx = threadIdx.x; idx < 4 * NF; idx += 256)
        rows_s[idx] = src[rowBase * NF + idx];   // contiguous
    __syncthreads();
    int tx = threadIdx.x & 63;   // d
    int ty = threadIdx.x >> 6;   // row within block
    float acc = 0.f;
    #pragma unroll
    for (int k = 0; k < NF; ++k)
        acc += rows_s[ty * NF + k] * pjs[k * VD + tx];
    g_featT[y][tx * ROWS + rowBase + ty] = acc;
}

// ---------------- K5: fused score-GEMM + argmax ----------------
// For each row tile (128 rows), sweep all 8192 codebook cols in 64-wide tiles,
// keep running argmax in registers. BM=128, BN=64, K=64 staged once.
// smem: As[k][m] ld=128 (32KB) + Bs[k][n] ld=64 (16KB) = 48KB exactly.
__global__ void __launch_bounds__(256, 2)
score_kernel(float* __restrict__ out) {
    __shared__ float pool[12288];
    float* As = pool;            // 64*128
    float* Bs = pool + 8192;     // 64*64
    int cb = blockIdx.y;
    const float* featT = g_featT[cb];
    const float* cbnT  = g_cbnT[cb];
    int rowBase = blockIdx.x * 128;     // 152 * 128 = 19456 exact
    int tx = threadIdx.x & 15;          // col group (4 cols)
    int ty = threadIdx.x >> 4;          // row group (8 rows)

    // Load A tile (k-major feats): As[k*128 + m], vectorized, conflict-free
    for (int idx = threadIdx.x; idx < 64 * 128 / 4; idx += 256) {
        int k = idx >> 5, f4 = idx & 31;
        *reinterpret_cast<float4*>(&As[k * 128 + f4 * 4]) =
            *reinterpret_cast<const float4*>(&featT[k * ROWS + rowBase + f4 * 4]);
    }

    float best[8];
    int bidx[8];
    #pragma unroll
    for (int i = 0; i < 8; ++i) { best[i] = -CUDART_INF_F; bidx[i] = 0; }

    for (int t = 0; t < NCB / 64; ++t) {
        int colBase = t * 64;
        __syncthreads();   // also covers the As load on first iteration
        for (int idx = threadIdx.x; idx < 64 * 64 / 4; idx += 256) {
            int k = idx >> 4, f4 = idx & 15;
            *reinterpret_cast<float4*>(&Bs[k * 64 + f4 * 4]) =
                *reinterpret_cast<const float4*>(&cbnT[k * NCB + colBase + f4 * 4]);
        }
        __syncthreads();

        float acc[8][4] = {};
        #pragma unroll 8
        for (int k = 0; k < 64; ++k) {
            float4 a0 = *reinterpret_cast<const float4*>(&As[k * 128 + ty * 8]);
            float4 a1 = *reinterpret_cast<const float4*>(&As[k * 128 + ty * 8 + 4]);
            float4 b  = *reinterpret_cast<const float4*>(&Bs[k * 64 + tx * 4]);
            float av[8] = {a0.x, a0.y, a0.z, a0.w, a1.x, a1.y, a1.z, a1.w};
            float bv[4] = {b.x, b.y, b.z, b.w};
            #pragma unroll
            for (int i = 0; i < 8; ++i)
                #pragma unroll
                for (int j = 0; j < 4; ++j)
                    acc[i][j] += av[i] * bv[j];
        }
        // running argmax; strict '>' + increasing col order = first-max (jnp.argmax) semantics
        #pragma unroll
        for (int i = 0; i < 8; ++i)
            #pragma unroll
            for (int j = 0; j < 4; ++j) {
                float v = acc[i][j];
                if (v > best[i]) { best[i] = v; bidx[i] = colBase + tx * 4 + j; }
            }
    }

    // Cross-thread reduce (16 partials per row), reuse As region
    __syncthreads();
    float* sVal = pool;
    int*   sIdx = reinterpret_cast<int*>(pool + 2048);
    #pragma unroll
    for (int i = 0; i < 8; ++i) {
        int m = ty * 8 + i;
        sVal[m * 16 + tx] = best[i];
        sIdx[m * 16 + tx] = bidx[i];
    }
    __syncthreads();
    if (threadIdx.x < 128) {
        int m = threadIdx.x;
        float bv = sVal[m * 16];
        int   bi = sIdx[m * 16];
        #pragma unroll
        for (int t = 1; t < 16; ++t) {
            float v = sVal[m * 16 + t];
            int   id = sIdx[m * 16 + t];
            if (v > bv || (v == bv && id < bi)) { bv = v; bi = id; }
        }
        // __output__ hypothesis: float32 buffer; indices <= 8191 are exactly representable
        out[cb * ROWS + rowBase + m] = (float)bi;
    }
}

// ---------------- launch ----------------
extern "C" void kernel_launch(void* const* d_in, const int* in_sizes, int n_in,
                              void* d_out, int out_size) {
    // Robust input dispatch BY ELEMENT COUNT (immune to metadata ordering):
    //   x: 38,912,000   proj_*: 6,464 (amp first, then phase)   codebook_*: 524,288 (amp, phase)
    const float* x          = nullptr;
    const float* proj_amp   = nullptr;
    const float* proj_phase = nullptr;
    const float* cb_amp     = nullptr;
    const float* cb_phase   = nullptr;
    for (int i = 0; i < n_in; ++i) {
        const float* p = (const float*)d_in[i];
        int sz = in_sizes[i];
        if (sz == SZ_X) {
            x = p;
        } else if (sz == SZ_PROJ) {
            if (!proj_amp) proj_amp = p; else proj_phase = p;
        } else if (sz == SZ_CB) {
            if (!cb_amp) cb_amp = p; else cb_phase = p;
        }
    }
    float* out = (float*)d_out;

    build_w_kernel<<<(INPUT_DIM * FFTW + 255) / 256, 256>>>();
    norm_cb_kernel<<<dim3(NCB / 8, 2), 256>>>(cb_amp, cb_phase);
    dft_gemm_kernel<<<dim3(ROWS / 64, 4), 256>>>(x);
    ampphase_kernel<<<(ROWS * NF + 255) / 256, 256>>>();
    proj_kernel<<<dim3(ROWS / 4, 2), 256>>>(proj_amp, proj_phase);
    score_kernel<<<dim3(ROWS / 128, 2), 256>>>(out);
}